// round 14
// baseline (speedup 1.0000x reference)
#include <cuda_runtime.h>
#include <cuda_bf16.h>
#include <math.h>
#include <stdint.h>

// ---------------- problem constants ----------------
#define IN_DIM     768
#define DIM        512
#define NUM_BINS   16
#define SEQ_N      2048
#define DAY_LENGTH 64
#define M_TOTAL    16384

// ---------------- tiling ----------------
#define BM       128
#define BN       128
#define BK       64            // K elems per stage
#define STAGES   2
#define NTHREADS 256
#define KTILES   (IN_DIM / BK) // 12

// 8 warps: 4 (M) x 2 (N), warp tile 32x64
#define MT 2                   // 2 x m16
#define NT 8                   // 8 x n8

// A stored as fp32 in smem (converted to bf16 at fragment load).
// A row: 64 f32 = 256 B + 16 pad = 272 B. B row: 64 bf16 = 128 B + 16 pad = 144 B.
#define ROW_A       272
#define ROW_BB      144
#define A_STAGE     (BM * ROW_A)            // 34816
#define B_STAGE     (BN * ROW_BB)           // 18432
#define STAGE_BYTES (A_STAGE + B_STAGE)     // 53248
#define SMEM_BYTES  (STAGES * STAGE_BYTES)  // 106496 -> 2 CTAs/SM

// bf16 scratch for freqs only (device global -- no allocation)
__device__ __align__(16) __nv_bfloat16 g_fb[(size_t)DIM * IN_DIM];

__device__ __forceinline__ uint32_t smem_u32(const void* p) {
    uint32_t a;
    asm("{ .reg .u64 t; cvta.to.shared.u64 t, %1; cvt.u32.u64 %0, t; }" : "=r"(a) : "l"(p));
    return a;
}
__device__ __forceinline__ void cp16(uint32_t dst, const void* src) {
    asm volatile("cp.async.cg.shared.global [%0], [%1], 16;" :: "r"(dst), "l"(src) : "memory");
}
__device__ __forceinline__ float tanh_approx(float x) {
    float y;
    asm("tanh.approx.f32 %0, %1;" : "=f"(y) : "f"(x));
    return y;
}
// pack two f32 into bf16x2 (lo = first, hi = second), round-to-nearest-even
__device__ __forceinline__ uint32_t pack_bf16(float lo, float hi) {
    uint32_t r;
    asm("cvt.rn.bf16x2.f32 %0, %1, %2;" : "=r"(r) : "f"(hi), "f"(lo));
    return r;
}
#define LDSM4(r, addr)                                                          \
    asm volatile("ldmatrix.sync.aligned.m8n8.x4.shared.b16 {%0,%1,%2,%3}, [%4];"\
        : "=r"((r)[0]), "=r"((r)[1]), "=r"((r)[2]), "=r"((r)[3]) : "r"(addr))

__device__ __forceinline__ void mma_bf16(float* c, const uint32_t* a, const uint32_t* b) {
    asm volatile(
        "mma.sync.aligned.m16n8k16.row.col.f32.bf16.bf16.f32 "
        "{%0,%1,%2,%3}, {%4,%5,%6,%7}, {%8,%9}, {%0,%1,%2,%3};"
        : "+f"(c[0]), "+f"(c[1]), "+f"(c[2]), "+f"(c[3])
        : "r"(a[0]), "r"(a[1]), "r"(a[2]), "r"(a[3]), "r"(b[0]), "r"(b[1]));
}

// ---------------- tiny prepass: freqs fp32 -> bf16 ----------------
#define CVT_UNROLL 4
__global__ void cvt_f_kernel(const float4* __restrict__ fr, int n4) {
    int base = blockIdx.x * (blockDim.x * CVT_UNROLL) + threadIdx.x;
    #pragma unroll
    for (int j = 0; j < CVT_UNROLL; j++) {
        int i = base + j * blockDim.x;
        if (i < n4) {
            float4 v = fr[i];
            __nv_bfloat162 lo = __floats2bfloat162_rn(v.x, v.y);
            __nv_bfloat162 hi = __floats2bfloat162_rn(v.z, v.w);
            uint2 o;
            o.x = *reinterpret_cast<uint32_t*>(&lo);
            o.y = *reinterpret_cast<uint32_t*>(&hi);
            reinterpret_cast<uint2*>(g_fb)[i] = o;
        }
    }
}

// ---------------- main fused kernel (x converted in-register) ----------------
__global__ __launch_bounds__(NTHREADS, 2)
void atom_bf16_kernel(const float* __restrict__ x,        // [M, IN_DIM] fp32
                      const float* __restrict__ phase,    // [DIM]
                      const float* __restrict__ heights,  // [DIM, NUM_BINS]
                      const float* __restrict__ bias,     // [DIM]
                      const int*   __restrict__ offset_p,
                      float*       __restrict__ out)      // [M, DIM]
{
    extern __shared__ char smemc[];
    const uint32_t sbase = smem_u32(smemc);
    const int tid  = threadIdx.x;
    const int wid  = tid >> 5;
    const int lane = tid & 31;
    const int wm   = wid & 3;          // 4 x 32 = 128 M
    const int wn   = wid >> 2;         // 2 x 64 = 128 N
    const int f0   = blockIdx.x * BN;
    const int m0   = blockIdx.y * BM;
    const int lr   = lane >> 2;        // 0..7
    const int lc   = lane & 3;         // 0..3

    // A fragment base (fp32 in smem): rows wm*32+mt*16+lr(+8), cols 2lc(+1,+8,+9)
    const uint32_t a_thread = (uint32_t)((wm * 32 + lr) * ROW_A + lc * 8);
    // B ldmatrix lane offset (bf16), B region starts at A_STAGE
    const int lrow = lane & 7, lmat = lane >> 3;
    const uint32_t b_lane = (uint32_t)(A_STAGE
                                       + (wn * 64 + (lmat >> 1) * 8 + lrow) * ROW_BB
                                       + (lmat & 1) * 16);

    float acc[MT][NT][4];
    #pragma unroll
    for (int i = 0; i < MT; i++)
        #pragma unroll
        for (int j = 0; j < NT; j++)
            #pragma unroll
            for (int q = 0; q < 4; q++) acc[i][j][q] = 0.0f;

    auto load_stage = [&](int s, int kc) {
        const uint32_t base = sbase + (uint32_t)s * STAGE_BYTES;
        const float* ag = x + (size_t)m0 * IN_DIM + kc * BK;
        #pragma unroll
        for (int j = 0; j < 8; j++) {   // A: 128 rows x 16 chunks of 16B = 2048
            int idx = tid + j * NTHREADS;
            int row = idx >> 4, c = idx & 15;
            cp16(base + row * ROW_A + c * 16, ag + (size_t)row * IN_DIM + c * 4);
        }
        const __nv_bfloat16* bg = g_fb + (size_t)f0 * IN_DIM + kc * BK;
        const uint32_t bbase = base + A_STAGE;
        #pragma unroll
        for (int j = 0; j < 4; j++) {   // B: 128 rows x 8 chunks = 1024
            int idx = tid + j * NTHREADS;
            int row = idx >> 3, c = idx & 7;
            cp16(bbase + row * ROW_BB + c * 16, bg + (size_t)row * IN_DIM + c * 8);
        }
        asm volatile("cp.async.commit_group;" ::: "memory");
    };

    uint32_t af[MT][4], bf[4][4];

    auto hmma_all = [&]() {
        #pragma unroll
        for (int mt = 0; mt < MT; mt++)
            #pragma unroll
            for (int p = 0; p < 4; p++) {
                mma_bf16(acc[mt][2 * p + 0], af[mt], &bf[p][0]);
                mma_bf16(acc[mt][2 * p + 1], af[mt], &bf[p][2]);
            }
    };

    // prologue: 1 stage in flight
    load_stage(0, 0);

    for (int kc = 0; kc < KTILES; kc++) {
        asm volatile("cp.async.wait_group 0;" ::: "memory");
        __syncthreads();
        if (kc + 1 < KTILES)            // overlaps the 256 HMMAs below
            load_stage((kc + 1) & 1, kc + 1);

        const uint32_t stg = (uint32_t)(kc & 1) * STAGE_BYTES;
        const char* abase = smemc + stg + a_thread;

        #pragma unroll
        for (int step = 0; step < 4; step++) {
            // A fragments: fp32 LDS -> bf16x2 (round-nearest-even == prepass)
            #pragma unroll
            for (int mt = 0; mt < MT; mt++) {
                const char* p = abase + mt * (16 * ROW_A) + step * 64;
                float2 v0 = *reinterpret_cast<const float2*>(p);
                float2 v1 = *reinterpret_cast<const float2*>(p + 8 * ROW_A);
                float2 v2 = *reinterpret_cast<const float2*>(p + 32);
                float2 v3 = *reinterpret_cast<const float2*>(p + 8 * ROW_A + 32);
                af[mt][0] = pack_bf16(v0.x, v0.y);
                af[mt][1] = pack_bf16(v1.x, v1.y);
                af[mt][2] = pack_bf16(v2.x, v2.y);
                af[mt][3] = pack_bf16(v3.x, v3.y);
            }
            // B fragments via ldmatrix
            #pragma unroll
            for (int p = 0; p < 4; p++)
                LDSM4(bf[p], sbase + stg + b_lane + p * (16 * ROW_BB) + step * 32);
            hmma_all();
        }
    }
    __syncthreads();

    // ---- epilogue tables in freed smem ----
    float2* stab = reinterpret_cast<float2*>(smemc);                 // [BN][NUM_BINS]
    float*  ptab = reinterpret_cast<float*>(smemc + BN * NUM_BINS * 8);
    float*  btab = ptab + BN;
    float2* rtab = reinterpret_cast<float2*>(btab + BN);             // [BN/2]
    if (tid < BN) {
        int fg = f0 + tid;
        float s1 = 0.0f, s2 = 0.0f;
        float2* row = stab + tid * NUM_BINS;
        #pragma unroll
        for (int k = 0; k < NUM_BINS; k++) {
            float h  = heights[fg * NUM_BINS + k];
            float wv = (h > 20.0f) ? h : log1pf(expf(h));  // softplus (accurate)
            s1 += wv;
            s2 += (float)k * (1.0f / 15.0f) * wv;
            row[k] = make_float2(s1, s2);
        }
        ptab[tid] = phase[fg];
        btab[tid] = bias[fg];
        if (tid < BN / 2) {
            float hv = (float)(f0 + 2 * tid) * (1.0f / (float)DIM);
            rtab[tid] = make_float2(exp2f(-13.287712379549449f * hv),   // 10000^-half
                                    exp2f(-16.609640474436812f * hv));  // 100000^-half
        }
    }
    __syncthreads();

    // ---- fused epilogue: sin -> sigmoid(tanh) -> spline -> bias -> RoPE ----
    const int offset = *offset_p;

    #pragma unroll
    for (int mt = 0; mt < MT; mt++) {
        #pragma unroll
        for (int o = 0; o < 2; o++) {
            const int m = m0 + wm * 32 + mt * 16 + o * 8 + lr;
            const int nseq  = m & (SEQ_N - 1);
            const float tf0 = (float)(nseq + offset);
            const float days  = floorf(tf0 * (1.0f / (float)DAY_LENGTH));
            const float hours = tf0 - days * (float)DAY_LENGTH;

            #pragma unroll
            for (int nt = 0; nt < NT; nt++) {
                const int fl = wn * 64 + nt * 8 + lc * 2;  // even local f
                float vv[2];
                #pragma unroll
                for (int e = 0; e < 2; e++) {
                    float basis = acc[mt][nt][o * 2 + e] + ptab[fl + e];
                    float s = __sinf(basis);
                    float u = fmaf(tanh_approx(0.5f * s), 0.5f, 0.5f);  // sigmoid
                    int bin = (int)(u * 15.0f);
                    bin = bin < 0 ? 0 : (bin > 15 ? 15 : bin);
                    float2 S = stab[(fl + e) * NUM_BINS + bin];
                    vv[e] = fmaf(u, S.x, -S.y) + btab[fl + e];
                }
                float2 rf = rtab[fl >> 1];
                float sn, cs;
                __sincosf(fmaf(hours, rf.x, days * rf.y), &sn, &cs);
                float2 o2;
                o2.x = vv[0] * cs - vv[1] * sn;
                o2.y = vv[0] * sn + vv[1] * cs;
                *reinterpret_cast<float2*>(out + (size_t)m * DIM + f0 + fl) = o2;
            }
        }
    }
}

// ---------------- launch ----------------
extern "C" void kernel_launch(void* const* d_in, const int* in_sizes, int n_in,
                              void* d_out, int out_size)
{
    const float* x       = (const float*)d_in[0];
    const float* freqs   = (const float*)d_in[1];
    const float* phase   = (const float*)d_in[2];
    const float* heights = (const float*)d_in[3];
    const float* bias    = (const float*)d_in[4];
    const int*   offset  = (const int*)d_in[5];
    float*       out     = (float*)d_out;

    const int M = in_sizes[0] / IN_DIM;              // 16384

    const int fn4 = DIM * IN_DIM / 4;                // 98,304
    cvt_f_kernel<<<(fn4 + 256 * CVT_UNROLL - 1) / (256 * CVT_UNROLL), 256>>>(
        (const float4*)freqs, fn4);

    // Stateless + graph-capture safe (not a stream op).
    cudaFuncSetAttribute(atom_bf16_kernel,
                         cudaFuncAttributeMaxDynamicSharedMemorySize, SMEM_BYTES);

    dim3 grid(DIM / BN, M / BM);                     // (4, 128) = 512 CTAs
    atom_bf16_kernel<<<grid, NTHREADS, SMEM_BYTES>>>(x, phase, heights, bias,
                                                     offset, out);
}

// round 15
// speedup vs baseline: 1.1477x; 1.1477x over previous
#include <cuda_runtime.h>
#include <cuda_bf16.h>
#include <math.h>
#include <stdint.h>

// ---------------- problem constants ----------------
#define IN_DIM     768
#define DIM        512
#define NUM_BINS   16
#define SEQ_N      2048
#define DAY_LENGTH 64
#define M_TOTAL    16384

// ---------------- tiling (R13 mainloop, A converted at STS time) ----------------
#define BM       128
#define BN       128
#define BK       64            // K elems per stage
#define STAGES   3
#define NTHREADS 256
#define KTILES   (IN_DIM / BK) // 12

// 8 warps: 4 (M) x 2 (N), warp tile 32x64
#define MT 2                   // 2 x m16
#define NT 8                   // 8 x n8

// smem: bf16 rows of 72 halves (144 B) -> ldmatrix 8-row groups conflict-free
#define ROW_B       144
#define A_ROWS      BM
#define B_ROWS      BN
#define STAGE_BYTES ((A_ROWS + B_ROWS) * ROW_B)   // 36864
#define SMEM_BYTES  (STAGES * STAGE_BYTES)        // 110592 -> 2 CTAs/SM

// bf16 scratch for freqs only (device global -- no allocation)
__device__ __align__(16) __nv_bfloat16 g_fb[(size_t)DIM * IN_DIM];

__device__ __forceinline__ uint32_t smem_u32(const void* p) {
    uint32_t a;
    asm("{ .reg .u64 t; cvta.to.shared.u64 t, %1; cvt.u32.u64 %0, t; }" : "=r"(a) : "l"(p));
    return a;
}
__device__ __forceinline__ void cp16(uint32_t dst, const void* src) {
    asm volatile("cp.async.cg.shared.global [%0], [%1], 16;" :: "r"(dst), "l"(src) : "memory");
}
__device__ __forceinline__ float tanh_approx(float x) {
    float y;
    asm("tanh.approx.f32 %0, %1;" : "=f"(y) : "f"(x));
    return y;
}
// pack two f32 -> bf16x2 (lo first), round-to-nearest-even (== old prepass)
__device__ __forceinline__ uint32_t pack_bf16(float lo, float hi) {
    uint32_t r;
    asm("cvt.rn.bf16x2.f32 %0, %1, %2;" : "=r"(r) : "f"(hi), "f"(lo));
    return r;
}
__device__ __forceinline__ void sts64(uint32_t dst, uint32_t lo, uint32_t hi) {
    asm volatile("st.shared.v2.b32 [%0], {%1, %2};" :: "r"(dst), "r"(lo), "r"(hi) : "memory");
}
#define LDSM4(r, addr)                                                          \
    asm volatile("ldmatrix.sync.aligned.m8n8.x4.shared.b16 {%0,%1,%2,%3}, [%4];"\
        : "=r"((r)[0]), "=r"((r)[1]), "=r"((r)[2]), "=r"((r)[3]) : "r"(addr))

__device__ __forceinline__ void mma_bf16(float* c, const uint32_t* a, const uint32_t* b) {
    asm volatile(
        "mma.sync.aligned.m16n8k16.row.col.f32.bf16.bf16.f32 "
        "{%0,%1,%2,%3}, {%4,%5,%6,%7}, {%8,%9}, {%0,%1,%2,%3};"
        : "+f"(c[0]), "+f"(c[1]), "+f"(c[2]), "+f"(c[3])
        : "r"(a[0]), "r"(a[1]), "r"(a[2]), "r"(a[3]), "r"(b[0]), "r"(b[1]));
}

// ---------------- tiny prepass: freqs fp32 -> bf16 (1.5 MB) ----------------
#define CVT_UNROLL 4
__global__ void cvt_f_kernel(const float4* __restrict__ fr, int n4) {
    int base = blockIdx.x * (blockDim.x * CVT_UNROLL) + threadIdx.x;
    #pragma unroll
    for (int j = 0; j < CVT_UNROLL; j++) {
        int i = base + j * blockDim.x;
        if (i < n4) {
            float4 v = fr[i];
            __nv_bfloat162 lo = __floats2bfloat162_rn(v.x, v.y);
            __nv_bfloat162 hi = __floats2bfloat162_rn(v.z, v.w);
            uint2 o;
            o.x = *reinterpret_cast<uint32_t*>(&lo);
            o.y = *reinterpret_cast<uint32_t*>(&hi);
            reinterpret_cast<uint2*>(g_fb)[i] = o;
        }
    }
}

// ---------------- main fused kernel (2 CTAs/SM; A: LDG fp32 -> bf16 STS) ----------------
__global__ __launch_bounds__(NTHREADS, 2)
void atom_bf16_kernel(const float* __restrict__ x,        // [M, IN_DIM] fp32
                      const float* __restrict__ phase,    // [DIM]
                      const float* __restrict__ heights,  // [DIM, NUM_BINS]
                      const float* __restrict__ bias,     // [DIM]
                      const int*   __restrict__ offset_p,
                      float*       __restrict__ out)      // [M, DIM]
{
    extern __shared__ float smem[];
    const uint32_t sbase = smem_u32(smem);
    const int tid  = threadIdx.x;
    const int wid  = tid >> 5;
    const int lane = tid & 31;
    const int wm   = wid & 3;          // 4 x 32 = 128 M
    const int wn   = wid >> 2;         // 2 x 64 = 128 N
    const int f0   = blockIdx.x * BN;
    const int m0   = blockIdx.y * BM;
    const int lr   = lane >> 2;        // 0..7
    const int lc   = lane & 3;         // 0..3

    // ldmatrix per-lane base offsets (identical to R13 layout)
    const int lrow = lane & 7, lmat = lane >> 3;
    const uint32_t a_lane = (uint32_t)((wm * 32 + (lmat & 1) * 8 + lrow) * ROW_B
                                       + ((lmat >> 1) * 8) * 2);
    const uint32_t b_lane = (uint32_t)(A_ROWS * ROW_B
                                       + (wn * 64 + (lmat >> 1) * 8 + lrow) * ROW_B
                                       + ((lmat & 1) * 8) * 2);

    // A conversion-load mapping: 2048 float4 chunks, 8 per thread (coalesced)
    const int a_row0 = tid >> 4;           // row advances by 16 per iter
    const int a_c    = tid & 15;           // float4 index within row (0..15)
    const float* xg  = x + (size_t)m0 * IN_DIM + a_row0 * IN_DIM + a_c * 4;
    const uint32_t a_sts0 = a_row0 * ROW_B + a_c * 8;   // bf16 dst within stage

    float acc[MT][NT][4];
    #pragma unroll
    for (int i = 0; i < MT; i++)
        #pragma unroll
        for (int j = 0; j < NT; j++)
            #pragma unroll
            for (int q = 0; q < 4; q++) acc[i][j][q] = 0.0f;

    auto loadB = [&](int s, int kc) {
        const __nv_bfloat16* bg = g_fb + (size_t)f0 * IN_DIM + kc * BK;
        const uint32_t bbase = sbase + (uint32_t)s * STAGE_BYTES + A_ROWS * ROW_B;
        #pragma unroll
        for (int j = 0; j < 4; j++) {   // B: 128 rows x 8 chunks of 16B = 1024
            int idx = tid + j * NTHREADS;
            int row = idx >> 3, c = idx & 7;
            cp16(bbase + row * ROW_B + c * 16, bg + (size_t)row * IN_DIM + c * 8);
        }
        asm volatile("cp.async.commit_group;" ::: "memory");
    };
    // synchronous A convert-load (prologue only)
    auto loadA_sync = [&](int s, int kc) {
        const uint32_t base = sbase + (uint32_t)s * STAGE_BYTES;
        const float* ag = xg + kc * BK;
        #pragma unroll
        for (int j = 0; j < 8; j++) {
            float4 v = *reinterpret_cast<const float4*>(ag + (size_t)j * 16 * IN_DIM);
            sts64(base + a_sts0 + j * 16 * ROW_B,
                  pack_bf16(v.x, v.y), pack_bf16(v.z, v.w));
        }
    };

    uint32_t af[MT][4], bf[4][4];

    auto ldsm_all = [&](uint32_t stg, uint32_t kb2) {
        #pragma unroll
        for (int mt = 0; mt < MT; mt++)
            LDSM4(af[mt], stg + a_lane + mt * (16 * ROW_B) + kb2);
        #pragma unroll
        for (int p = 0; p < 4; p++)
            LDSM4(bf[p], stg + b_lane + p * (16 * ROW_B) + kb2);
    };
    auto hmma_all = [&]() {
        #pragma unroll
        for (int mt = 0; mt < MT; mt++)
            #pragma unroll
            for (int p = 0; p < 4; p++) {
                mma_bf16(acc[mt][2 * p + 0], af[mt], &bf[p][0]);
                mma_bf16(acc[mt][2 * p + 1], af[mt], &bf[p][2]);
            }
    };

    // prologue: stages 0,1 (A synchronous, B async)
    loadA_sync(0, 0);
    loadA_sync(1, 1);
    loadB(0, 0);
    loadB(1, 1);
    asm volatile("cp.async.wait_group 1;" ::: "memory");
    __syncthreads();

    for (int kc = 0; kc < KTILES; kc++) {
        const uint32_t stg = sbase + (uint32_t)(kc % STAGES) * STAGE_BYTES;
        const bool pf = (kc + 2 < KTILES);

        ldsm_all(stg, 0);               // k16 step 0
        // issue A LDG batch for stage kc+2 (latency hidden under step-0 HMMAs)
        float4 av[8];
        if (pf) {
            const float* ag = xg + (kc + 2) * BK;
            #pragma unroll
            for (int j = 0; j < 8; j++)
                av[j] = *reinterpret_cast<const float4*>(ag + (size_t)j * 16 * IN_DIM);
        }
        hmma_all();
        if (pf) {                       // convert + STS, then B cp.async
            const uint32_t dbase = sbase + (uint32_t)((kc + 2) % STAGES) * STAGE_BYTES
                                   + a_sts0;
            #pragma unroll
            for (int j = 0; j < 8; j++)
                sts64(dbase + j * 16 * ROW_B,
                      pack_bf16(av[j].x, av[j].y), pack_bf16(av[j].z, av[j].w));
            loadB((kc + 2) % STAGES, kc + 2);
        }
        ldsm_all(stg, 32);              // k16 step 1
        hmma_all();
        ldsm_all(stg, 64);              // k16 step 2
        hmma_all();
        ldsm_all(stg, 96);              // k16 step 3
        hmma_all();

        if (pf)                   asm volatile("cp.async.wait_group 1;" ::: "memory");
        else if (kc + 1 < KTILES) asm volatile("cp.async.wait_group 0;" ::: "memory");
        if (kc + 1 < KTILES) __syncthreads();
    }
    __syncthreads();

    // ---- epilogue tables in freed smem ----
    float2* stab = reinterpret_cast<float2*>(smem);        // [BN][NUM_BINS] = 16 KB
    float*  ptab = smem + BN * NUM_BINS * 2;               // [BN]
    float*  btab = ptab + BN;                              // [BN]
    float2* rtab = reinterpret_cast<float2*>(btab + BN);   // [BN/2] (invh, invd)
    if (tid < BN) {
        int fg = f0 + tid;
        float s1 = 0.0f, s2 = 0.0f;
        float2* row = stab + tid * NUM_BINS;
        #pragma unroll
        for (int k = 0; k < NUM_BINS; k++) {
            float h  = heights[fg * NUM_BINS + k];
            float wv = (h > 20.0f) ? h : log1pf(expf(h));  // softplus (accurate)
            s1 += wv;
            s2 += (float)k * (1.0f / 15.0f) * wv;
            row[k] = make_float2(s1, s2);
        }
        ptab[tid] = phase[fg];
        btab[tid] = bias[fg];
        if (tid < BN / 2) {
            float hv = (float)(f0 + 2 * tid) * (1.0f / (float)DIM);
            rtab[tid] = make_float2(exp2f(-13.287712379549449f * hv),   // 10000^-half
                                    exp2f(-16.609640474436812f * hv));  // 100000^-half
        }
    }
    __syncthreads();

    // ---- fused epilogue: sin -> sigmoid(tanh) -> spline -> bias -> RoPE ----
    const int offset = *offset_p;

    #pragma unroll
    for (int mt = 0; mt < MT; mt++) {
        #pragma unroll
        for (int o = 0; o < 2; o++) {
            const int m = m0 + wm * 32 + mt * 16 + o * 8 + lr;
            const int nseq  = m & (SEQ_N - 1);
            const float tf0 = (float)(nseq + offset);
            const float days  = floorf(tf0 * (1.0f / (float)DAY_LENGTH));
            const float hours = tf0 - days * (float)DAY_LENGTH;

            #pragma unroll
            for (int nt = 0; nt < NT; nt++) {
                const int fl = wn * 64 + nt * 8 + lc * 2;  // even local f
                float vv[2];
                #pragma unroll
                for (int e = 0; e < 2; e++) {
                    float basis = acc[mt][nt][o * 2 + e] + ptab[fl + e];
                    float s = __sinf(basis);
                    float u = fmaf(tanh_approx(0.5f * s), 0.5f, 0.5f);  // sigmoid
                    int bin = (int)(u * 15.0f);
                    bin = bin < 0 ? 0 : (bin > 15 ? 15 : bin);
                    float2 S = stab[(fl + e) * NUM_BINS + bin];
                    vv[e] = fmaf(u, S.x, -S.y) + btab[fl + e];
                }
                float2 rf = rtab[fl >> 1];
                float sn, cs;
                __sincosf(fmaf(hours, rf.x, days * rf.y), &sn, &cs);
                float2 o2;
                o2.x = vv[0] * cs - vv[1] * sn;
                o2.y = vv[0] * sn + vv[1] * cs;
                *reinterpret_cast<float2*>(out + (size_t)m * DIM + f0 + fl) = o2;
            }
        }
    }
}

// ---------------- launch ----------------
extern "C" void kernel_launch(void* const* d_in, const int* in_sizes, int n_in,
                              void* d_out, int out_size)
{
    const float* x       = (const float*)d_in[0];
    const float* freqs   = (const float*)d_in[1];
    const float* phase   = (const float*)d_in[2];
    const float* heights = (const float*)d_in[3];
    const float* bias    = (const float*)d_in[4];
    const int*   offset  = (const int*)d_in[5];
    float*       out     = (float*)d_out;

    const int M = in_sizes[0] / IN_DIM;              // 16384

    const int fn4 = DIM * IN_DIM / 4;                // 98,304
    cvt_f_kernel<<<(fn4 + 256 * CVT_UNROLL - 1) / (256 * CVT_UNROLL), 256>>>(
        (const float4*)freqs, fn4);

    // Stateless + graph-capture safe (not a stream op).
    cudaFuncSetAttribute(atom_bf16_kernel,
                         cudaFuncAttributeMaxDynamicSharedMemorySize, SMEM_BYTES);

    dim3 grid(DIM / BN, M / BM);                     // (4, 128) = 512 CTAs
    atom_bf16_kernel<<<grid, NTHREADS, SMEM_BYTES>>>(x, phase, heights, bias,
                                                     offset, out);
}